// round 2
// baseline (speedup 1.0000x reference)
#include <cuda_runtime.h>

#define IN_DIM   256
#define OUT_DIM  256
#define N_KNOTS  9
#define NB       5          // N_BASIS
#define B_TILE   8          // batch rows per block
#define THREADS  256
#define SMEM_BYTES (IN_DIM * B_TILE * NB * 4)   // 40 KB

__global__ __launch_bounds__(THREADS, 4)
void kan_kernel(const float* __restrict__ x,
                const float* __restrict__ grids,
                const float* __restrict__ coef,
                float* __restrict__ y,
                float* __restrict__ acts)
{
    extern __shared__ float sbasis[];   // [IN_DIM][B_TILE][NB]
    const int t  = threadIdx.x;
    const int b0 = blockIdx.x * B_TILE;

    // ---------------- Phase 1: B-spline basis for i = t, all 8 rows -----------
    {
        const int i = t;
        float tk[N_KNOTS];
        #pragma unroll
        for (int k = 0; k < N_KNOTS; k++) tk[k] = grids[i * N_KNOTS + k];

        // reciprocal knot-difference denominators (depend only on i, not row)
        float iL1[7], iR1[7], iL2[6], iR2[6], iL3[5], iR3[5];
        #pragma unroll
        for (int j = 0; j < 7; j++) { iL1[j] = 1.f / (tk[j+1] - tk[j]); iR1[j] = 1.f / (tk[j+2] - tk[j+1]); }
        #pragma unroll
        for (int j = 0; j < 6; j++) { iL2[j] = 1.f / (tk[j+2] - tk[j]); iR2[j] = 1.f / (tk[j+3] - tk[j+1]); }
        #pragma unroll
        for (int j = 0; j < 5; j++) { iL3[j] = 1.f / (tk[j+3] - tk[j]); iR3[j] = 1.f / (tk[j+4] - tk[j+1]); }

        #pragma unroll
        for (int r = 0; r < B_TILE; r++) {
            const float xv = x[(size_t)(b0 + r) * IN_DIM + i];
            float bas[8];
            #pragma unroll
            for (int j = 0; j < 8; j++)
                bas[j] = (xv >= tk[j] && xv < tk[j+1]) ? 1.0f : 0.0f;
            #pragma unroll
            for (int j = 0; j < 7; j++)
                bas[j] = (xv - tk[j]) * iL1[j] * bas[j] + (tk[j+2] - xv) * iR1[j] * bas[j+1];
            #pragma unroll
            for (int j = 0; j < 6; j++)
                bas[j] = (xv - tk[j]) * iL2[j] * bas[j] + (tk[j+3] - xv) * iR2[j] * bas[j+1];
            #pragma unroll
            for (int j = 0; j < 5; j++)
                bas[j] = (xv - tk[j]) * iL3[j] * bas[j] + (tk[j+4] - xv) * iR3[j] * bas[j+1];

            float* sp = &sbasis[(i * B_TILE + r) * NB];
            #pragma unroll
            for (int n = 0; n < NB; n++) sp[n] = bas[n];
        }
    }
    __syncthreads();

    // ---------------- Phase 2: acts + y ---------------------------------------
    // thread -> 4 consecutive output cols (o4..o4+3) x 2 rows (rg2, rg2+1)
    const int og  = t & 63;
    const int o4  = og * 4;
    const int rg2 = (t >> 6) * 2;

    float4 acc[2];
    acc[0] = make_float4(0.f, 0.f, 0.f, 0.f);
    acc[1] = make_float4(0.f, 0.f, 0.f, 0.f);

    const float* cbase = coef + (size_t)o4 * NB;   // coef[i][o4][0]
    float* actp = acts + (size_t)(b0 + rg2) * (IN_DIM * OUT_DIM) + o4;

    for (int i = 0; i < IN_DIM; i++) {
        const float4* cp = reinterpret_cast<const float4*>(
            cbase + (size_t)i * (OUT_DIM * NB));
        const float4 c0 = cp[0], c1 = cp[1], c2 = cp[2], c3 = cp[3], c4 = cp[4];

        // 4 output cols x 5 basis coeffs (pure register renaming)
        const float cf[4][5] = {
            { c0.x, c0.y, c0.z, c0.w, c1.x },
            { c1.y, c1.z, c1.w, c2.x, c2.y },
            { c2.z, c2.w, c3.x, c3.y, c3.z },
            { c3.w, c4.x, c4.y, c4.z, c4.w }
        };

        const float* bp = &sbasis[(i * B_TILE + rg2) * NB];
        #pragma unroll
        for (int r = 0; r < 2; r++) {
            const float bb0 = bp[r*NB+0], bb1 = bp[r*NB+1], bb2 = bp[r*NB+2],
                        bb3 = bp[r*NB+3], bb4 = bp[r*NB+4];
            float4 v;
            v.x = bb0*cf[0][0] + bb1*cf[0][1] + bb2*cf[0][2] + bb3*cf[0][3] + bb4*cf[0][4];
            v.y = bb0*cf[1][0] + bb1*cf[1][1] + bb2*cf[1][2] + bb3*cf[1][3] + bb4*cf[1][4];
            v.z = bb0*cf[2][0] + bb1*cf[2][1] + bb2*cf[2][2] + bb3*cf[2][3] + bb4*cf[2][4];
            v.w = bb0*cf[3][0] + bb1*cf[3][1] + bb2*cf[3][2] + bb3*cf[3][3] + bb4*cf[3][4];

            // streaming store: acts is write-once, never re-read
            __stcs(reinterpret_cast<float4*>(
                actp + (size_t)r * (IN_DIM * OUT_DIM) + i * OUT_DIM), v);

            acc[r].x += v.x; acc[r].y += v.y; acc[r].z += v.z; acc[r].w += v.w;
        }
    }

    // y = sum over i (this block owns ALL i for its rows -> single write)
    float* yp = y + (size_t)(b0 + rg2) * OUT_DIM + o4;
    #pragma unroll
    for (int r = 0; r < 2; r++)
        *reinterpret_cast<float4*>(yp + (size_t)r * OUT_DIM) = acc[r];
}

extern "C" void kernel_launch(void* const* d_in, const int* in_sizes, int n_in,
                              void* d_out, int out_size)
{
    const float* x     = (const float*)d_in[0];
    const float* grids = (const float*)d_in[1];
    const float* coef  = (const float*)d_in[2];

    const int B = in_sizes[0] / IN_DIM;   // 4096

    float* y    = (float*)d_out;                          // (B, OUT_DIM) first
    float* acts = (float*)d_out + (size_t)B * OUT_DIM;    // (B, IN_DIM, OUT_DIM) second

    cudaFuncSetAttribute(kan_kernel,
                         cudaFuncAttributeMaxDynamicSharedMemorySize, SMEM_BYTES);
    kan_kernel<<<B / B_TILE, THREADS, SMEM_BYTES>>>(x, grids, coef, y, acts);
}

// round 3
// speedup vs baseline: 1.5589x; 1.5589x over previous
#include <cuda_runtime.h>

#define IN_DIM   256
#define OUT_DIM  256
#define N_KNOTS  9
#define NB       5
#define B_TILE   16
#define THREADS  256

#define SB_WORDS   (IN_DIM * NB * B_TILE)     // basis [i][n][r16] = 20480 words (80 KB)
#define SC_STRIDE  264                        // padded o-stride for coeff stage
#define SC_BUF     (NB * SC_STRIDE)           // 1320 words per buffer
#define SMEM_WORDS (SB_WORDS + 2 * SC_BUF)
#define SMEM_BYTES (SMEM_WORDS * 4)           // 92480 B -> 2 CTAs/SM

__global__ __launch_bounds__(THREADS, 2)
void kan_kernel(const float* __restrict__ x,
                const float* __restrict__ grids,
                const float* __restrict__ coef,
                float* __restrict__ y,
                float* __restrict__ acts)
{
    extern __shared__ float smem[];
    float* sbasis = smem;               // [i][n][r]  word = (i*5+n)*16 + r
    float* scoef  = smem + SB_WORDS;    // 2 x [n][264] word = buf*1320 + n*264 + o

    const int t  = threadIdx.x;
    const int b0 = blockIdx.x * B_TILE;

    // ------- Phase 1: basis for i = t, 16 rows (rotated r to dodge bank conflicts)
    {
        const int i = t;
        float tk[N_KNOTS];
        #pragma unroll
        for (int k = 0; k < N_KNOTS; k++) tk[k] = grids[i * N_KNOTS + k];

        float iL1[7], iR1[7], iL2[6], iR2[6], iL3[5], iR3[5];
        #pragma unroll
        for (int j = 0; j < 7; j++) { iL1[j] = 1.f / (tk[j+1] - tk[j]); iR1[j] = 1.f / (tk[j+2] - tk[j+1]); }
        #pragma unroll
        for (int j = 0; j < 6; j++) { iL2[j] = 1.f / (tk[j+2] - tk[j]); iR2[j] = 1.f / (tk[j+3] - tk[j+1]); }
        #pragma unroll
        for (int j = 0; j < 5; j++) { iL3[j] = 1.f / (tk[j+3] - tk[j]); iR3[j] = 1.f / (tk[j+4] - tk[j+1]); }

        const int rot = i & 15;
        #pragma unroll
        for (int rr = 0; rr < B_TILE; rr++) {
            const int r = (rr + rot) & 15;
            const float xv = x[(size_t)(b0 + r) * IN_DIM + i];
            float bas[8];
            #pragma unroll
            for (int j = 0; j < 8; j++)
                bas[j] = (xv >= tk[j] && xv < tk[j+1]) ? 1.0f : 0.0f;
            #pragma unroll
            for (int j = 0; j < 7; j++)
                bas[j] = (xv - tk[j]) * iL1[j] * bas[j] + (tk[j+2] - xv) * iR1[j] * bas[j+1];
            #pragma unroll
            for (int j = 0; j < 6; j++)
                bas[j] = (xv - tk[j]) * iL2[j] * bas[j] + (tk[j+3] - xv) * iR2[j] * bas[j+1];
            #pragma unroll
            for (int j = 0; j < 5; j++)
                bas[j] = (xv - tk[j]) * iL3[j] * bas[j] + (tk[j+4] - xv) * iR3[j] * bas[j+1];

            #pragma unroll
            for (int n = 0; n < NB; n++)
                sbasis[(i * NB + n) * B_TILE + r] = bas[n];
        }
    }

    // ------- Coeff staging offsets (fixed per thread): idx = t + 256k
    int dstw[NB];
    #pragma unroll
    for (int k = 0; k < NB; k++) {
        const int idx = t + THREADS * k;        // 0..1279
        dstw[k] = (idx % NB) * SC_STRIDE + (idx / NB);
    }

    // preload coeff row 0 into buffer 0 (same sync publishes basis + coeff)
    {
        float p[NB];
        #pragma unroll
        for (int k = 0; k < NB; k++) p[k] = coef[t + THREADS * k];
        #pragma unroll
        for (int k = 0; k < NB; k++) scoef[dstw[k]] = p[k];
    }
    __syncthreads();

    // ------- Phase 2: thread -> 4 consecutive o (o4..o4+3) x 4 rows (rg4..rg4+3)
    const int o4  = (t & 63) * 4;
    const int rg4 = (t >> 6) * 4;

    float4 acc[4];
    #pragma unroll
    for (int r = 0; r < 4; r++) acc[r] = make_float4(0.f, 0.f, 0.f, 0.f);

    float* actp = acts + (size_t)(b0 + rg4) * (IN_DIM * OUT_DIM) + o4;

    for (int i = 0; i < IN_DIM; i++) {
        const int buf = i & 1;

        // prefetch next coeff row (coalesced: lane-consecutive floats)
        float p[NB];
        if (i + 1 < IN_DIM) {
            const float* src = coef + (size_t)(i + 1) * (OUT_DIM * NB);
            #pragma unroll
            for (int k = 0; k < NB; k++) p[k] = src[t + THREADS * k];
        }

        // coeff from smem: [n][o4..o4+3], conflict-free LDS.128
        float4 cf[NB];
        #pragma unroll
        for (int n = 0; n < NB; n++)
            cf[n] = *reinterpret_cast<const float4*>(
                &scoef[buf * SC_BUF + n * SC_STRIDE + o4]);

        // basis: 4 rows at once per n, broadcast LDS.128
        float4 bs[NB];
        #pragma unroll
        for (int n = 0; n < NB; n++)
            bs[n] = *reinterpret_cast<const float4*>(
                &sbasis[(i * NB + n) * B_TILE + rg4]);

        #pragma unroll
        for (int r = 0; r < 4; r++) {
            const float b0r = reinterpret_cast<const float*>(&bs[0])[r];
            const float b1r = reinterpret_cast<const float*>(&bs[1])[r];
            const float b2r = reinterpret_cast<const float*>(&bs[2])[r];
            const float b3r = reinterpret_cast<const float*>(&bs[3])[r];
            const float b4r = reinterpret_cast<const float*>(&bs[4])[r];
            float4 v;
            v.x = b0r*cf[0].x + b1r*cf[1].x + b2r*cf[2].x + b3r*cf[3].x + b4r*cf[4].x;
            v.y = b0r*cf[0].y + b1r*cf[1].y + b2r*cf[2].y + b3r*cf[3].y + b4r*cf[4].y;
            v.z = b0r*cf[0].z + b1r*cf[1].z + b2r*cf[2].z + b3r*cf[3].z + b4r*cf[4].z;
            v.w = b0r*cf[0].w + b1r*cf[1].w + b2r*cf[2].w + b3r*cf[3].w + b4r*cf[4].w;

            __stcs(reinterpret_cast<float4*>(
                actp + (size_t)r * (IN_DIM * OUT_DIM) + i * OUT_DIM), v);

            acc[r].x += v.x; acc[r].y += v.y; acc[r].z += v.z; acc[r].w += v.w;
        }

        // publish next coeff row into the other buffer
        if (i + 1 < IN_DIM) {
            float* dst = scoef + (buf ^ 1) * SC_BUF;
            #pragma unroll
            for (int k = 0; k < NB; k++) dst[dstw[k]] = p[k];
        }
        __syncthreads();
    }

    // ------- y = sum over i (block owns all i for its rows)
    float* yp = y + (size_t)(b0 + rg4) * OUT_DIM + o4;
    #pragma unroll
    for (int r = 0; r < 4; r++)
        *reinterpret_cast<float4*>(yp + (size_t)r * OUT_DIM) = acc[r];
}

extern "C" void kernel_launch(void* const* d_in, const int* in_sizes, int n_in,
                              void* d_out, int out_size)
{
    const float* x     = (const float*)d_in[0];
    const float* grids = (const float*)d_in[1];
    const float* coef  = (const float*)d_in[2];

    const int B = in_sizes[0] / IN_DIM;   // 4096

    float* y    = (float*)d_out;
    float* acts = (float*)d_out + (size_t)B * OUT_DIM;

    cudaFuncSetAttribute(kan_kernel,
                         cudaFuncAttributeMaxDynamicSharedMemorySize, SMEM_BYTES);
    kan_kernel<<<B / B_TILE, THREADS, SMEM_BYTES>>>(x, grids, coef, y, acts);
}